// round 2
// baseline (speedup 1.0000x reference)
#include <cuda_runtime.h>
#include <cstdint>

#define NN   32768
#define EE   524288
#define BBG  64
#define NPGC 512
#define CCH  256
#define FINC 128

// ---------------- scratch (static device globals; no allocation) ----------------
__device__ float g_buf0[NN * CCH];   // GEMM output / agg input (h_lin)
__device__ float g_h1[NN * CCH];     // layer-1 output (post ELU)
__device__ float g_h2[NN * CCH];     // layer-2 output (post ELU)
__device__ float g_es[NN * 4];
__device__ float g_ed[NN * 4];
__device__ int   g_cnt[NN];
__device__ int   g_cur[NN];
__device__ int   g_off[NN + 1];
__device__ int   g_srcs[EE];
__device__ float g_vvec[CCH];
__device__ float g_l1[NN];
__device__ float g_l2[NN];

// ---------------- small helpers ----------------
__device__ __forceinline__ float lrelu02(float x) { return x >= 0.f ? x : 0.2f * x; }

__device__ __forceinline__ unsigned int fkey_asc(float f) {
    unsigned int u = __float_as_uint(f);
    return (u & 0x80000000u) ? ~u : (u | 0x80000000u);
}

// ---------------- CSR build ----------------
__global__ void k_zero2() {
    int i = blockIdx.x * blockDim.x + threadIdx.x;
    if (i < NN) { g_cnt[i] = 0; g_cur[i] = 0; }
}

__global__ void k_hist(const int* __restrict__ dst) {
    int i = blockIdx.x * blockDim.x + threadIdx.x;
    if (i < EE) atomicAdd(&g_cnt[dst[i]], 1);
}

__global__ void k_scan() {
    __shared__ int sums[1024];
    int tid = threadIdx.x;
    int base = tid * 32;
    int s = 0;
    for (int i = 0; i < 32; i++) s += g_cnt[base + i];
    sums[tid] = s;
    __syncthreads();
    // Hillis-Steele inclusive scan over 1024
    for (int d = 1; d < 1024; d <<= 1) {
        int v = (tid >= d) ? sums[tid - d] : 0;
        __syncthreads();
        sums[tid] += v;
        __syncthreads();
    }
    int excl = (tid == 0) ? 0 : sums[tid - 1];
    int run = excl;
    for (int i = 0; i < 32; i++) { g_off[base + i] = run; run += g_cnt[base + i]; }
    if (tid == 1023) g_off[NN] = sums[1023];
}

__global__ void k_scatter(const int* __restrict__ src, const int* __restrict__ dst) {
    int i = blockIdx.x * blockDim.x + threadIdx.x;
    if (i < EE) {
        int d = dst[i];
        int p = atomicAdd(&g_cur[d], 1);
        g_srcs[g_off[d] + p] = src[i];
    }
}

// ---------------- fp32 SGEMM: C[M,256] = A[M,K] @ B[K,256] ----------------
// 128x128 tile, BK=8, 256 threads, 8x8 microtile.
__global__ void __launch_bounds__(256) k_gemm(const float* __restrict__ A,
                                              const float* __restrict__ B,
                                              float* __restrict__ C, int K) {
    __shared__ float As[8][128];
    __shared__ float Bs[8][128];
    int tid = threadIdx.x;
    int bm = blockIdx.x * 128;
    int bn = blockIdx.y * 128;
    int arow = tid >> 1, acol = (tid & 1) * 4;
    int brow = tid >> 5, bcol = (tid & 31) * 4;
    int tx = tid & 15, ty = tid >> 4;
    float acc[8][8];
#pragma unroll
    for (int i = 0; i < 8; i++)
#pragma unroll
        for (int j = 0; j < 8; j++) acc[i][j] = 0.f;

    for (int k0 = 0; k0 < K; k0 += 8) {
        float4 av = *(const float4*)(A + (size_t)(bm + arow) * K + k0 + acol);
        float4 bv = *(const float4*)(B + (size_t)(k0 + brow) * 256 + bn + bcol);
        As[acol + 0][arow] = av.x;
        As[acol + 1][arow] = av.y;
        As[acol + 2][arow] = av.z;
        As[acol + 3][arow] = av.w;
        *(float4*)&Bs[brow][bcol] = bv;
        __syncthreads();
#pragma unroll
        for (int kk = 0; kk < 8; kk++) {
            float ra[8], rb[8];
            *(float4*)&ra[0] = *(float4*)&As[kk][ty * 8];
            *(float4*)&ra[4] = *(float4*)&As[kk][ty * 8 + 4];
            *(float4*)&rb[0] = *(float4*)&Bs[kk][tx * 8];
            *(float4*)&rb[4] = *(float4*)&Bs[kk][tx * 8 + 4];
#pragma unroll
            for (int i = 0; i < 8; i++)
#pragma unroll
                for (int j = 0; j < 8; j++) acc[i][j] += ra[i] * rb[j];
        }
        __syncthreads();
    }
#pragma unroll
    for (int i = 0; i < 8; i++) {
        float4 s0 = make_float4(acc[i][0], acc[i][1], acc[i][2], acc[i][3]);
        float4 s1 = make_float4(acc[i][4], acc[i][5], acc[i][6], acc[i][7]);
        float* cp = C + (size_t)(bm + ty * 8 + i) * 256 + bn + tx * 8;
        *(float4*)cp = s0;
        *(float4*)(cp + 4) = s1;
    }
}

// ---------------- es/ed: per-node per-head attention dot products ----------------
__global__ void k_esed(const float* __restrict__ h, const float* __restrict__ a_src,
                       const float* __restrict__ a_dst) {
    int warp = (blockIdx.x * blockDim.x + threadIdx.x) >> 5;
    int lane = threadIdx.x & 31;
    if (warp >= NN) return;
    int hd = lane >> 3;
    int off = (lane & 7) * 8;
    const float4* hp = (const float4*)(h + (size_t)warp * 256 + hd * 64 + off);
    const float4* ap = (const float4*)(a_src + hd * 64 + off);
    const float4* bp = (const float4*)(a_dst + hd * 64 + off);
    float4 x0 = hp[0], x1 = hp[1];
    float4 a0 = ap[0], a1 = ap[1];
    float4 b0 = bp[0], b1 = bp[1];
    float ps = x0.x * a0.x + x0.y * a0.y + x0.z * a0.z + x0.w * a0.w +
               x1.x * a1.x + x1.y * a1.y + x1.z * a1.z + x1.w * a1.w;
    float pd = x0.x * b0.x + x0.y * b0.y + x0.z * b0.z + x0.w * b0.w +
               x1.x * b1.x + x1.y * b1.y + x1.z * b1.z + x1.w * b1.w;
#pragma unroll
    for (int d = 1; d < 8; d <<= 1) {
        ps += __shfl_xor_sync(0xFFFFFFFFu, ps, d);
        pd += __shfl_xor_sync(0xFFFFFFFFu, pd, d);
    }
    if ((lane & 7) == 0) {
        g_es[warp * 4 + hd] = ps;
        g_ed[warp * 4 + hd] = pd;
    }
}

// ---------------- GAT edge softmax + aggregation (one warp per dst node) ----------------
__global__ void k_agg(const float* __restrict__ h, const float* __restrict__ bias,
                      float* __restrict__ out) {
    int n = (blockIdx.x * blockDim.x + threadIdx.x) >> 5;
    int lane = threadIdx.x & 31;
    if (n >= NN) return;
    int hd = lane >> 3;

    float edh[4], esn[4];
#pragma unroll
    for (int q = 0; q < 4; q++) { edh[q] = g_ed[n * 4 + q]; esn[q] = g_es[n * 4 + q]; }

    int s0 = g_off[n], s1 = g_off[n + 1];

    // pass 1: per-head max (include self-loop)
    float m[4];
#pragma unroll
    for (int q = 0; q < 4; q++) m[q] = lrelu02(esn[q] + edh[q]);
    for (int i = s0 + lane; i < s1; i += 32) {
        int s = g_srcs[i];
#pragma unroll
        for (int q = 0; q < 4; q++) {
            float e = lrelu02(g_es[s * 4 + q] + edh[q]);
            m[q] = fmaxf(m[q], e);
        }
    }
#pragma unroll
    for (int q = 0; q < 4; q++)
#pragma unroll
        for (int d = 16; d > 0; d >>= 1) m[q] = fmaxf(m[q], __shfl_xor_sync(0xFFFFFFFFu, m[q], d));

    // pass 2: weighted accumulate; lane owns channels lane*8..lane*8+7 (single head per lane)
    float myED = edh[hd];
    float myM = m[hd];
    float4 acc0 = make_float4(0, 0, 0, 0), acc1 = make_float4(0, 0, 0, 0);
    float den = 0.f;

    for (int i = s0; i < s1; i++) {
        int s = g_srcs[i];
        float e = lrelu02(g_es[s * 4 + hd] + myED);
        float w = expf(e - myM);
        den += w;
        const float4* hp = (const float4*)(h + (size_t)s * 256 + lane * 8);
        float4 v0 = hp[0], v1 = hp[1];
        acc0.x += w * v0.x; acc0.y += w * v0.y; acc0.z += w * v0.z; acc0.w += w * v0.w;
        acc1.x += w * v1.x; acc1.y += w * v1.y; acc1.z += w * v1.z; acc1.w += w * v1.w;
    }
    // self-loop
    {
        float e = lrelu02(esn[hd] + myED);
        float w = expf(e - myM);
        den += w;
        const float4* hp = (const float4*)(h + (size_t)n * 256 + lane * 8);
        float4 v0 = hp[0], v1 = hp[1];
        acc0.x += w * v0.x; acc0.y += w * v0.y; acc0.z += w * v0.z; acc0.w += w * v0.w;
        acc1.x += w * v1.x; acc1.y += w * v1.y; acc1.z += w * v1.z; acc1.w += w * v1.w;
    }
    float inv = 1.f / (den + 1e-16f);
    const float* bp = bias + lane * 8;
    float o[8];
    o[0] = acc0.x * inv + bp[0]; o[1] = acc0.y * inv + bp[1];
    o[2] = acc0.z * inv + bp[2]; o[3] = acc0.w * inv + bp[3];
    o[4] = acc1.x * inv + bp[4]; o[5] = acc1.y * inv + bp[5];
    o[6] = acc1.z * inv + bp[6]; o[7] = acc1.w * inv + bp[7];
#pragma unroll
    for (int q = 0; q < 8; q++) o[q] = o[q] > 0.f ? o[q] : expm1f(o[q]);
    float* op = out + (size_t)n * 256 + lane * 8;
    *(float4*)op = make_float4(o[0], o[1], o[2], o[3]);
    *(float4*)(op + 4) = make_float4(o[4], o[5], o[6], o[7]);
}

// ---------------- v = p1_tw @ p2_sw (for pool-2 score shortcut) ----------------
__global__ void k_vvec(const float* __restrict__ p1_tw, const float* __restrict__ p2_sw) {
    int k = threadIdx.x;
    float s = 0.f;
    for (int c = 0; c < 256; c++) s += p1_tw[k * 256 + c] * p2_sw[c];
    g_vvec[k] = s;
}

// ---------------- per-node pooling score logits ----------------
__global__ void k_scores(const float* __restrict__ h2, const float* __restrict__ p1_sw) {
    int n = (blockIdx.x * blockDim.x + threadIdx.x) >> 5;
    int lane = threadIdx.x & 31;
    if (n >= NN) return;
    const float4* hp = (const float4*)(h2 + (size_t)n * 256 + lane * 8);
    const float4* w1 = (const float4*)(p1_sw + lane * 8);
    const float4* w2 = (const float4*)(g_vvec + lane * 8);
    float4 h0 = hp[0], h1 = hp[1];
    float4 a0 = w1[0], a1 = w1[1];
    float4 b0 = w2[0], b1 = w2[1];
    float s1 = h0.x * a0.x + h0.y * a0.y + h0.z * a0.z + h0.w * a0.w +
               h1.x * a1.x + h1.y * a1.y + h1.z * a1.z + h1.w * a1.w;
    float s2 = h0.x * b0.x + h0.y * b0.y + h0.z * b0.z + h0.w * b0.w +
               h1.x * b1.x + h1.y * b1.y + h1.z * b1.z + h1.w * b1.w;
#pragma unroll
    for (int d = 16; d > 0; d >>= 1) {
        s1 += __shfl_xor_sync(0xFFFFFFFFu, s1, d);
        s2 += __shfl_xor_sync(0xFFFFFFFFu, s2, d);
    }
    if (lane == 0) { g_l1[n] = s1; g_l2[n] = s2; }
}

// ---------------- per-graph: double top-k select + mean + classifier ----------------
__device__ __forceinline__ void bitonic_sort(unsigned long long* keys, int n, int tid, int nthreads) {
    for (int k = 2; k <= n; k <<= 1) {
        for (int j = k >> 1; j > 0; j >>= 1) {
            for (int t = tid; t < n; t += nthreads) {
                int ixj = t ^ j;
                if (ixj > t) {
                    bool up = ((t & k) == 0);
                    unsigned long long a = keys[t], b = keys[ixj];
                    if (up ? (a > b) : (a < b)) { keys[t] = b; keys[ixj] = a; }
                }
            }
            __syncthreads();
        }
    }
}

__global__ void __launch_bounds__(256) k_pool(
    const float* __restrict__ h2,
    const float* __restrict__ p1_tw, const float* __restrict__ p1_tb,
    const float* __restrict__ p2_tw, const float* __restrict__ p2_tb,
    const float* __restrict__ c1w, const float* __restrict__ c1b,
    const float* __restrict__ c2w, const float* __restrict__ c2b,
    float* __restrict__ out) {
    __shared__ unsigned long long keys[512];
    __shared__ int idx1[256];
    __shared__ int sel[128];
    __shared__ float bufA[256];
    __shared__ float bufB[256];
    __shared__ float zbuf[64];
    __shared__ float lg[2];

    int g = blockIdx.x;
    int tid = threadIdx.x;

    // stage 1: top-256 of 512 by l1 (desc value, asc index)
    for (int t = tid; t < 512; t += 256) {
        float v = g_l1[g * NPGC + t];
        keys[t] = ((unsigned long long)(~fkey_asc(v)) << 32) | (unsigned int)t;
    }
    __syncthreads();
    bitonic_sort(keys, 512, tid, 256);
    idx1[tid] = (int)(keys[tid] & 0xFFFFFFFFu);
    __syncthreads();

    // stage 2: top-128 of those 256 by l2 (tie-break by pool1 rank)
    {
        float v = g_l2[g * NPGC + idx1[tid]];
        keys[tid] = ((unsigned long long)(~fkey_asc(v)) << 32) | (unsigned int)tid;
    }
    __syncthreads();
    bitonic_sort(keys, 256, tid, 256);
    if (tid < 128) sel[tid] = idx1[(int)(keys[tid] & 0xFFFFFFFFu)];
    __syncthreads();

    // mean of selected h2 rows
    {
        float acc = 0.f;
        for (int j = 0; j < 128; j++) acc += h2[(size_t)(g * NPGC + sel[j]) * 256 + tid];
        bufA[tid] = acc * (1.f / 128.f);
    }
    __syncthreads();
    // t1 = g @ p1_tw + p1_tb
    {
        float s = p1_tb[tid];
        for (int k = 0; k < 256; k++) s += bufA[k] * p1_tw[k * 256 + tid];
        bufB[tid] = s;
    }
    __syncthreads();
    // t2 = t1 @ p2_tw + p2_tb
    {
        float s = p2_tb[tid];
        for (int k = 0; k < 256; k++) s += bufB[k] * p2_tw[k * 256 + tid];
        bufA[tid] = s;
    }
    __syncthreads();
    // z = relu(t2 @ c1w + c1b)
    if (tid < 64) {
        float s = c1b[tid];
        for (int k = 0; k < 256; k++) s += bufA[k] * c1w[k * 64 + tid];
        zbuf[tid] = fmaxf(s, 0.f);
    }
    __syncthreads();
    if (tid < 2) {
        float s = c2b[tid];
        for (int k = 0; k < 64; k++) s += zbuf[k] * c2w[k * 2 + tid];
        lg[tid] = s;
    }
    __syncthreads();
    if (tid < 2) {
        float mx = fmaxf(lg[0], lg[1]);
        float lse = mx + logf(expf(lg[0] - mx) + expf(lg[1] - mx));
        out[g * 2 + tid] = lg[tid] - lse;
    }
}

// ---------------- launch ----------------
extern "C" void kernel_launch(void* const* d_in, const int* in_sizes, int n_in,
                              void* d_out, int out_size) {
    const float* x      = (const float*)d_in[0];
    const int*   ei     = (const int*)d_in[1];
    const float* W1     = (const float*)d_in[3];
    const float* a_src1 = (const float*)d_in[4];
    const float* a_dst1 = (const float*)d_in[5];
    const float* b1     = (const float*)d_in[6];
    const float* W2     = (const float*)d_in[7];
    const float* a_src2 = (const float*)d_in[8];
    const float* a_dst2 = (const float*)d_in[9];
    const float* b2     = (const float*)d_in[10];
    const float* p1_sw  = (const float*)d_in[11];
    const float* p1_tw  = (const float*)d_in[13];
    const float* p1_tb  = (const float*)d_in[14];
    const float* p2_sw  = (const float*)d_in[15];
    const float* p2_tw  = (const float*)d_in[17];
    const float* p2_tb  = (const float*)d_in[18];
    const float* c1w    = (const float*)d_in[19];
    const float* c1b    = (const float*)d_in[20];
    const float* c2w    = (const float*)d_in[21];
    const float* c2b    = (const float*)d_in[22];
    float* out = (float*)d_out;

    const int* src = ei;
    const int* dst = ei + EE;

    float* hlin; cudaGetSymbolAddress((void**)&hlin, g_buf0);
    float* h1;   cudaGetSymbolAddress((void**)&h1, g_h1);
    float* h2;   cudaGetSymbolAddress((void**)&h2, g_h2);

    // CSR build (dst-sorted adjacency)
    k_zero2<<<NN / 256, 256>>>();
    k_hist<<<EE / 256, 256>>>(dst);
    k_scan<<<1, 1024>>>();
    k_scatter<<<EE / 256, 256>>>(src, dst);

    // layer 1
    k_gemm<<<dim3(NN / 128, 2), 256>>>(x, W1, hlin, FINC);
    k_esed<<<NN / 8, 256>>>(hlin, a_src1, a_dst1);
    k_agg<<<NN / 8, 256>>>(hlin, b1, h1);

    // layer 2
    k_gemm<<<dim3(NN / 128, 2), 256>>>(h1, W2, hlin, CCH);
    k_esed<<<NN / 8, 256>>>(hlin, a_src2, a_dst2);
    k_agg<<<NN / 8, 256>>>(hlin, b2, h2);

    // pooling scores + final head
    k_vvec<<<1, 256>>>(p1_tw, p2_sw);
    k_scores<<<NN / 8, 256>>>(h2, p1_sw);
    k_pool<<<BBG, 256>>>(h2, p1_tw, p1_tb, p2_tw, p2_tb, c1w, c1b, c2w, c2b, out);
}

// round 4
// speedup vs baseline: 1.0586x; 1.0586x over previous
#include <cuda_runtime.h>
#include <cstdint>

#define NN   32768
#define EE   524288
#define BBG  64
#define NPGC 512
#define CCH  256
#define FINC 128

// ---------------- scratch (static device globals; no allocation) ----------------
__device__ float g_buf0[NN * CCH];   // GEMM output (h_lin)
__device__ float g_h1[NN * CCH];     // layer-1 output (post ELU)
__device__ float g_h2[NN * CCH];     // layer-2 output (post ELU)
__device__ float g_es[NN * 4];
__device__ float g_ed[NN * 4];
__device__ int   g_cnt[NN];
__device__ int   g_cur[NN];
__device__ int   g_off[NN + 1];
__device__ int   g_srcs[EE];
__device__ float g_vvec[CCH];
__device__ float g_l1[NN];
__device__ float g_l2[NN];

__device__ __forceinline__ float lrelu02(float x) { return x >= 0.f ? x : 0.2f * x; }

__device__ __forceinline__ unsigned int fkey_asc(float f) {
    unsigned int u = __float_as_uint(f);
    return (u & 0x80000000u) ? ~u : (u | 0x80000000u);
}

// ---------------- CSR build ----------------
__global__ void k_zero2() {
    int i = blockIdx.x * blockDim.x + threadIdx.x;
    if (i < NN) { g_cnt[i] = 0; g_cur[i] = 0; }
}

__global__ void k_hist(const int* __restrict__ dst) {
    int i = blockIdx.x * blockDim.x + threadIdx.x;
    if (i < EE) atomicAdd(&g_cnt[dst[i]], 1);
}

__global__ void k_scan() {
    __shared__ int sums[1024];
    int tid = threadIdx.x;
    int base = tid * 32;
    int s = 0;
    for (int i = 0; i < 32; i++) s += g_cnt[base + i];
    sums[tid] = s;
    __syncthreads();
    for (int d = 1; d < 1024; d <<= 1) {
        int v = (tid >= d) ? sums[tid - d] : 0;
        __syncthreads();
        sums[tid] += v;
        __syncthreads();
    }
    int excl = (tid == 0) ? 0 : sums[tid - 1];
    int run = excl;
    for (int i = 0; i < 32; i++) { g_off[base + i] = run; run += g_cnt[base + i]; }
    if (tid == 1023) g_off[NN] = sums[1023];
}

__global__ void k_scatter(const int* __restrict__ src, const int* __restrict__ dst) {
    int i = blockIdx.x * blockDim.x + threadIdx.x;
    if (i < EE) {
        int d = dst[i];
        int p = atomicAdd(&g_cur[d], 1);
        g_srcs[g_off[d] + p] = src[i];
    }
}

// ---------------- double-buffered SGEMM with fused es/ed epilogue ----------------
// C[M,256] = A[M,K] @ B[K,256]; 128x128 tile, BK=8, 256 threads, 8x8 microtile.
// Epilogue: es[n,h] = sum_c C[n,c]*a_src[c], ed likewise (each 128-col block = 2 heads).
template <int NSTEPS>
__global__ void __launch_bounds__(256) k_gemm_fused(
    const float* __restrict__ A, const float* __restrict__ B, float* __restrict__ C,
    const float* __restrict__ a_src, const float* __restrict__ a_dst) {
    __shared__ float As[2][8][128];
    __shared__ float Bs[2][8][128];
    const int K = NSTEPS * 8;
    int tid = threadIdx.x;
    int bm = blockIdx.x * 128;
    int bn = blockIdx.y * 128;
    int arow = tid >> 1, acol = (tid & 1) * 4;
    int brow = tid >> 5, bcol = (tid & 31) * 4;
    int tx = tid & 15, ty = tid >> 4;

    const float* Ap = A + (size_t)(bm + arow) * K + acol;
    const float* Bp = B + (size_t)brow * 256 + bn + bcol;

    float4 av = *(const float4*)Ap;
    float4 bv = *(const float4*)Bp;

    float acc[8][8];
#pragma unroll
    for (int i = 0; i < 8; i++)
#pragma unroll
        for (int j = 0; j < 8; j++) acc[i][j] = 0.f;

    As[0][acol + 0][arow] = av.x;
    As[0][acol + 1][arow] = av.y;
    As[0][acol + 2][arow] = av.z;
    As[0][acol + 3][arow] = av.w;
    *(float4*)&Bs[0][brow][bcol] = bv;
    __syncthreads();

#pragma unroll 1
    for (int s = 0; s < NSTEPS; s++) {
        int cur = s & 1;
        if (s + 1 < NSTEPS) {
            av = *(const float4*)(Ap + (s + 1) * 8);
            bv = *(const float4*)(Bp + (size_t)(s + 1) * 8 * 256);
        }
#pragma unroll
        for (int kk = 0; kk < 8; kk++) {
            float ra[8], rb[8];
            *(float4*)&ra[0] = *(float4*)&As[cur][kk][ty * 8];
            *(float4*)&ra[4] = *(float4*)&As[cur][kk][ty * 8 + 4];
            *(float4*)&rb[0] = *(float4*)&Bs[cur][kk][tx * 8];
            *(float4*)&rb[4] = *(float4*)&Bs[cur][kk][tx * 8 + 4];
#pragma unroll
            for (int i = 0; i < 8; i++)
#pragma unroll
                for (int j = 0; j < 8; j++) acc[i][j] += ra[i] * rb[j];
        }
        if (s + 1 < NSTEPS) {
            int nxt = cur ^ 1;
            As[nxt][acol + 0][arow] = av.x;
            As[nxt][acol + 1][arow] = av.y;
            As[nxt][acol + 2][arow] = av.z;
            As[nxt][acol + 3][arow] = av.w;
            *(float4*)&Bs[nxt][brow][bcol] = bv;
        }
        __syncthreads();
    }

    // write C
#pragma unroll
    for (int i = 0; i < 8; i++) {
        float* cp = C + (size_t)(bm + ty * 8 + i) * 256 + bn + tx * 8;
        *(float4*)cp = make_float4(acc[i][0], acc[i][1], acc[i][2], acc[i][3]);
        *(float4*)(cp + 4) = make_float4(acc[i][4], acc[i][5], acc[i][6], acc[i][7]);
    }

    // fused es/ed: per-thread partial dot over its 8 cols, 8-lane shuffle reduce
    float asv[8], adv[8];
    *(float4*)&asv[0] = *(const float4*)(a_src + bn + tx * 8);
    *(float4*)&asv[4] = *(const float4*)(a_src + bn + tx * 8 + 4);
    *(float4*)&adv[0] = *(const float4*)(a_dst + bn + tx * 8);
    *(float4*)&adv[4] = *(const float4*)(a_dst + bn + tx * 8 + 4);
    int lane = tid & 31;
    int head = (bn >> 6) + ((lane >> 3) & 1);
#pragma unroll
    for (int i = 0; i < 8; i++) {
        float ps = 0.f, pd = 0.f;
#pragma unroll
        for (int j = 0; j < 8; j++) { ps += acc[i][j] * asv[j]; pd += acc[i][j] * adv[j]; }
#pragma unroll
        for (int d = 1; d < 8; d <<= 1) {
            ps += __shfl_xor_sync(0xFFFFFFFFu, ps, d);
            pd += __shfl_xor_sync(0xFFFFFFFFu, pd, d);
        }
        if ((lane & 7) == 0) {
            int row = bm + ty * 8 + i;
            g_es[row * 4 + head] = ps;
            g_ed[row * 4 + head] = pd;
        }
    }
}

// ---------------- GAT edge softmax + aggregation: single pass, no max ----------------
// softmax is shift-invariant; logits are leaky-relu of O(1) dots -> exp safe.
__global__ void k_agg(const float* __restrict__ h, const float* __restrict__ bias,
                      float* __restrict__ out) {
    int n = (blockIdx.x * blockDim.x + threadIdx.x) >> 5;
    int lane = threadIdx.x & 31;
    if (n >= NN) return;
    int hd = lane >> 3;

    float myED = g_ed[n * 4 + hd];
    float esn = g_es[n * 4 + hd];
    int s0 = g_off[n], s1 = g_off[n + 1];

    float4 acc0, acc1;
    float den;
    // self-loop
    {
        float w = __expf(lrelu02(esn + myED));
        den = w;
        const float4* hp = (const float4*)(h + (size_t)n * 256 + lane * 8);
        float4 v0 = hp[0], v1 = hp[1];
        acc0 = make_float4(w * v0.x, w * v0.y, w * v0.z, w * v0.w);
        acc1 = make_float4(w * v1.x, w * v1.y, w * v1.z, w * v1.w);
    }

    for (int base = s0; base < s1; base += 8) {
        int cnt = s1 - base;
        int ss[8];
        float ee[8];
#pragma unroll
        for (int u = 0; u < 8; u++) ss[u] = (u < cnt) ? g_srcs[base + u] : n;
#pragma unroll
        for (int u = 0; u < 8; u++) ee[u] = g_es[ss[u] * 4 + hd];
#pragma unroll
        for (int u = 0; u < 8; u++) {
            float w = (u < cnt) ? __expf(lrelu02(ee[u] + myED)) : 0.f;
            den += w;
            const float4* hp = (const float4*)(h + (size_t)ss[u] * 256 + lane * 8);
            float4 v0 = hp[0], v1 = hp[1];
            acc0.x += w * v0.x; acc0.y += w * v0.y; acc0.z += w * v0.z; acc0.w += w * v0.w;
            acc1.x += w * v1.x; acc1.y += w * v1.y; acc1.z += w * v1.z; acc1.w += w * v1.w;
        }
    }

    float inv = 1.f / (den + 1e-16f);
    const float* bp = bias + lane * 8;
    float o[8];
    o[0] = acc0.x * inv + bp[0]; o[1] = acc0.y * inv + bp[1];
    o[2] = acc0.z * inv + bp[2]; o[3] = acc0.w * inv + bp[3];
    o[4] = acc1.x * inv + bp[4]; o[5] = acc1.y * inv + bp[5];
    o[6] = acc1.z * inv + bp[6]; o[7] = acc1.w * inv + bp[7];
#pragma unroll
    for (int q = 0; q < 8; q++) o[q] = o[q] > 0.f ? o[q] : expm1f(o[q]);
    float* op = out + (size_t)n * 256 + lane * 8;
    *(float4*)op = make_float4(o[0], o[1], o[2], o[3]);
    *(float4*)(op + 4) = make_float4(o[4], o[5], o[6], o[7]);
}

// ---------------- v = p1_tw @ p2_sw ----------------
__global__ void k_vvec(const float* __restrict__ p1_tw, const float* __restrict__ p2_sw) {
    int k = threadIdx.x;
    float s = 0.f;
    for (int c = 0; c < 256; c++) s += p1_tw[k * 256 + c] * p2_sw[c];
    g_vvec[k] = s;
}

// ---------------- per-node pooling score logits ----------------
__global__ void k_scores(const float* __restrict__ h2, const float* __restrict__ p1_sw) {
    int n = (blockIdx.x * blockDim.x + threadIdx.x) >> 5;
    int lane = threadIdx.x & 31;
    if (n >= NN) return;
    const float4* hp = (const float4*)(h2 + (size_t)n * 256 + lane * 8);
    const float4* w1 = (const float4*)(p1_sw + lane * 8);
    const float4* w2 = (const float4*)(g_vvec + lane * 8);
    float4 h0 = hp[0], h1 = hp[1];
    float4 a0 = w1[0], a1 = w1[1];
    float4 b0 = w2[0], b1 = w2[1];
    float s1 = h0.x * a0.x + h0.y * a0.y + h0.z * a0.z + h0.w * a0.w +
               h1.x * a1.x + h1.y * a1.y + h1.z * a1.z + h1.w * a1.w;
    float s2 = h0.x * b0.x + h0.y * b0.y + h0.z * b0.z + h0.w * b0.w +
               h1.x * b1.x + h1.y * b1.y + h1.z * b1.z + h1.w * b1.w;
#pragma unroll
    for (int d = 16; d > 0; d >>= 1) {
        s1 += __shfl_xor_sync(0xFFFFFFFFu, s1, d);
        s2 += __shfl_xor_sync(0xFFFFFFFFu, s2, d);
    }
    if (lane == 0) { g_l1[n] = s1; g_l2[n] = s2; }
}

// ---------------- per-graph: double top-k select + mean + classifier ----------------
__device__ __forceinline__ void bitonic_sort(unsigned long long* keys, int n, int tid, int nthreads) {
    for (int k = 2; k <= n; k <<= 1) {
        for (int j = k >> 1; j > 0; j >>= 1) {
            for (int t = tid; t < n; t += nthreads) {
                int ixj = t ^ j;
                if (ixj > t) {
                    bool up = ((t & k) == 0);
                    unsigned long long a = keys[t], b = keys[ixj];
                    if (up ? (a > b) : (a < b)) { keys[t] = b; keys[ixj] = a; }
                }
            }
            __syncthreads();
        }
    }
}

__global__ void __launch_bounds__(256) k_pool(
    const float* __restrict__ h2,
    const float* __restrict__ p1_tw, const float* __restrict__ p1_tb,
    const float* __restrict__ p2_tw, const float* __restrict__ p2_tb,
    const float* __restrict__ c1w, const float* __restrict__ c1b,
    const float* __restrict__ c2w, const float* __restrict__ c2b,
    float* __restrict__ out) {
    __shared__ unsigned long long keys[512];
    __shared__ int idx1[256];
    __shared__ int sel[128];
    __shared__ float bufA[256];
    __shared__ float bufB[256];
    __shared__ float zbuf[64];
    __shared__ float lg[2];

    int g = blockIdx.x;
    int tid = threadIdx.x;

    for (int t = tid; t < 512; t += 256) {
        float v = g_l1[g * NPGC + t];
        keys[t] = ((unsigned long long)(~fkey_asc(v)) << 32) | (unsigned int)t;
    }
    __syncthreads();
    bitonic_sort(keys, 512, tid, 256);
    idx1[tid] = (int)(keys[tid] & 0xFFFFFFFFu);
    __syncthreads();

    {
        float v = g_l2[g * NPGC + idx1[tid]];
        keys[tid] = ((unsigned long long)(~fkey_asc(v)) << 32) | (unsigned int)tid;
    }
    __syncthreads();
    bitonic_sort(keys, 256, tid, 256);
    if (tid < 128) sel[tid] = idx1[(int)(keys[tid] & 0xFFFFFFFFu)];
    __syncthreads();

    {
        float acc = 0.f;
        for (int j = 0; j < 128; j++) acc += h2[(size_t)(g * NPGC + sel[j]) * 256 + tid];
        bufA[tid] = acc * (1.f / 128.f);
    }
    __syncthreads();
    {
        float s = p1_tb[tid];
        for (int k = 0; k < 256; k++) s += bufA[k] * p1_tw[k * 256 + tid];
        bufB[tid] = s;
    }
    __syncthreads();
    {
        float s = p2_tb[tid];
        for (int k = 0; k < 256; k++) s += bufB[k] * p2_tw[k * 256 + tid];
        bufA[tid] = s;
    }
    __syncthreads();
    if (tid < 64) {
        float s = c1b[tid];
        for (int k = 0; k < 256; k++) s += bufA[k] * c1w[k * 64 + tid];
        zbuf[tid] = fmaxf(s, 0.f);
    }
    __syncthreads();
    if (tid < 2) {
        float s = c2b[tid];
        for (int k = 0; k < 64; k++) s += zbuf[k] * c2w[k * 2 + tid];
        lg[tid] = s;
    }
    __syncthreads();
    if (tid < 2) {
        float mx = fmaxf(lg[0], lg[1]);
        float lse = mx + logf(expf(lg[0] - mx) + expf(lg[1] - mx));
        out[g * 2 + tid] = lg[tid] - lse;
    }
}

// ---------------- launch ----------------
extern "C" void kernel_launch(void* const* d_in, const int* in_sizes, int n_in,
                              void* d_out, int out_size) {
    const float* x      = (const float*)d_in[0];
    const int*   ei     = (const int*)d_in[1];
    const float* W1     = (const float*)d_in[3];
    const float* a_src1 = (const float*)d_in[4];
    const float* a_dst1 = (const float*)d_in[5];
    const float* b1     = (const float*)d_in[6];
    const float* W2     = (const float*)d_in[7];
    const float* a_src2 = (const float*)d_in[8];
    const float* a_dst2 = (const float*)d_in[9];
    const float* b2     = (const float*)d_in[10];
    const float* p1_sw  = (const float*)d_in[11];
    const float* p1_tw  = (const float*)d_in[13];
    const float* p1_tb  = (const float*)d_in[14];
    const float* p2_sw  = (const float*)d_in[15];
    const float* p2_tw  = (const float*)d_in[17];
    const float* p2_tb  = (const float*)d_in[18];
    const float* c1w    = (const float*)d_in[19];
    const float* c1b    = (const float*)d_in[20];
    const float* c2w    = (const float*)d_in[21];
    const float* c2b    = (const float*)d_in[22];
    float* out = (float*)d_out;

    const int* src = ei;
    const int* dst = ei + EE;

    float* hlin; cudaGetSymbolAddress((void**)&hlin, g_buf0);
    float* h1;   cudaGetSymbolAddress((void**)&h1, g_h1);
    float* h2;   cudaGetSymbolAddress((void**)&h2, g_h2);

    // CSR build (dst-sorted adjacency)
    k_zero2<<<NN / 256, 256>>>();
    k_hist<<<EE / 256, 256>>>(dst);
    k_scan<<<1, 1024>>>();
    k_scatter<<<EE / 256, 256>>>(src, dst);

    // layer 1 (GEMM + fused es/ed, then single-pass softmax-agg)
    k_gemm_fused<16><<<dim3(NN / 128, 2), 256>>>(x, W1, hlin, a_src1, a_dst1);
    k_agg<<<NN / 8, 256>>>(hlin, b1, h1);

    // layer 2
    k_gemm_fused<32><<<dim3(NN / 128, 2), 256>>>(h1, W2, hlin, a_src2, a_dst2);
    k_agg<<<NN / 8, 256>>>(hlin, b2, h2);

    // pooling scores + final head
    k_vvec<<<1, 256>>>(p1_tw, p2_sw);
    k_scores<<<NN / 8, 256>>>(h2, p1_sw);
    k_pool<<<BBG, 256>>>(h2, p1_tw, p1_tb, p2_tw, p2_tb, c1w, c1b, c2w, c2b, out);
}